// round 15
// baseline (speedup 1.0000x reference)
#include <cuda_runtime.h>
#include <cuda_fp16.h>
#include <math.h>
#include <stdint.h>

#define BB   2
#define SS   2048
#define DD   1024
#define HH   16
#define HDIM 64
#define ND   2
#define MM   (BB*SS)

// ---------------- scratch (device globals; no allocation allowed) ----------
__device__ float g_od[BB*HH*SS*HDIM];      // lam*(O0-O1), (b,h,s,hd)
__device__ float g_lamb[HH];
__device__ float g_stats[BB*HH*2];

__device__ __half g_xh [MM*DD];            // X hi/lo fp16
__device__ __half g_xl [MM*DD];
__device__ __half g_wth[6*DD*DD];          // W^T hi/lo: [q0,q1,k0,k1,v,o][n][k]
__device__ __half g_wtl[6*DD*DD];
__device__ __half g_x2h[MM*DD];            // normed activations hi/lo
__device__ __half g_x2l[MM*DD];

__device__ __half g_qh [ND*BB*HH*SS*HDIM]; // Q fp16, pre-scaled by 0.125
__device__ __half g_kh [ND*BB*HH*SS*HDIM]; // K fp16 (s,hd)
__device__ __half g_vh [BB*HH*SS*HDIM];    // V fp16

// ====================== PTX helpers (sm_80-baseline only) ==================
__device__ __forceinline__ uint32_t smem_u32(const void* p){
    uint32_t a;
    asm("{ .reg .u64 t; cvta.to.shared.u64 t, %1; cvt.u32.u64 %0, t; }"
        : "=r"(a) : "l"(p));
    return a;
}
__device__ __forceinline__ void cp16(uint32_t s, const void* g){
    asm volatile("cp.async.cg.shared.global [%0], [%1], 16;" :: "r"(s), "l"(g));
}
__device__ __forceinline__ void cp_commit(){ asm volatile("cp.async.commit_group;" ::: "memory"); }
__device__ __forceinline__ void cp_wait0(){ asm volatile("cp.async.wait_group 0;" ::: "memory"); }
__device__ __forceinline__ void cp_wait1(){ asm volatile("cp.async.wait_group 1;" ::: "memory"); }

__device__ __forceinline__ void ldsm4(uint32_t* r, uint32_t addr){
    asm volatile("ldmatrix.sync.aligned.m8n8.x4.shared.b16 {%0,%1,%2,%3}, [%4];"
        : "=r"(r[0]), "=r"(r[1]), "=r"(r[2]), "=r"(r[3]) : "r"(addr));
}
__device__ __forceinline__ void ldsm4t(uint32_t* r, uint32_t addr){
    asm volatile("ldmatrix.sync.aligned.m8n8.x4.trans.shared.b16 {%0,%1,%2,%3}, [%4];"
        : "=r"(r[0]), "=r"(r[1]), "=r"(r[2]), "=r"(r[3]) : "r"(addr));
}
__device__ __forceinline__ void mma16816(float* c, const uint32_t* a, const uint32_t* b){
    asm volatile(
        "mma.sync.aligned.m16n8k16.row.col.f32.f16.f16.f32 "
        "{%0,%1,%2,%3}, {%4,%5,%6,%7}, {%8,%9}, {%0,%1,%2,%3};"
        : "+f"(c[0]), "+f"(c[1]), "+f"(c[2]), "+f"(c[3])
        : "r"(a[0]), "r"(a[1]), "r"(a[2]), "r"(a[3]), "r"(b[0]), "r"(b[1]));
}
__device__ __forceinline__ uint32_t packh2(float a, float b){
    __half2 h = __floats2half2_rn(a, b);
    return *(uint32_t*)&h;
}

// ====================== prep: X -> fp16 hi/lo ==============================
__global__ void __launch_bounds__(256) convert_x_kernel(const float* __restrict__ X)
{
    int i = (blockIdx.x*256 + threadIdx.x)*4;
    float4 v = *(const float4*)&X[i];
    float a[4] = {v.x, v.y, v.z, v.w};
    __half hi[4], lo[4];
    #pragma unroll
    for (int c = 0; c < 4; c++) {
        hi[c] = __float2half_rn(a[c]);
        lo[c] = __float2half_rn(a[c] - __half2float(hi[c]));
    }
    *(__half2*)&g_xh[i]   = __halves2half2(hi[0], hi[1]);
    *(__half2*)&g_xh[i+2] = __halves2half2(hi[2], hi[3]);
    *(__half2*)&g_xl[i]   = __halves2half2(lo[0], lo[1]);
    *(__half2*)&g_xl[i+2] = __halves2half2(lo[2], lo[3]);
}

// ====================== prep: W -> W^T fp16 hi/lo ==========================
__global__ void __launch_bounds__(256) wtrans_kernel(
    const float* __restrict__ qw, const float* __restrict__ kw,
    const float* __restrict__ vw, const float* __restrict__ ow)
{
    __shared__ float t[32][33];
    const int w = blockIdx.z;
    const float* src;
    if      (w == 0) src = qw;
    else if (w == 1) src = qw + (size_t)DD*DD;
    else if (w == 2) src = kw;
    else if (w == 3) src = kw + (size_t)DD*DD;
    else if (w == 4) src = vw;
    else             src = ow;

    const int nb = blockIdx.x*32, kb = blockIdx.y*32;
    const int tx = threadIdx.x & 31, ty = threadIdx.x >> 5;

    #pragma unroll
    for (int i = 0; i < 4; i++)
        t[ty + i*8][tx] = src[(size_t)(kb + ty + i*8)*DD + nb + tx];
    __syncthreads();
    #pragma unroll
    for (int i = 0; i < 4; i++) {
        float v = t[tx][ty + i*8];
        __half hi = __float2half_rn(v);
        __half lo = __float2half_rn(v - __half2float(hi));
        size_t d = (size_t)w*DD*DD + (size_t)(nb + ty + i*8)*DD + kb + tx;
        g_wth[d] = hi;
        g_wtl[d] = lo;
    }
}

// ====================== HMMA fp16-split GEMM ===============================
// mode 0: Q/K single-pass (AhBh), V 2-pass (+AhBl).  mode 1: out, 3-pass.
#define KC      32
#define NCHUNK  (DD/KC)
#define ROWB    80
#define ARR_B   (128*ROWB)
#define ST_AH   0
#define ST_AL   (ARR_B)
#define ST_BH   (2*ARR_B)
#define ST_BL   (3*ARR_B)
#define STAGE_B (4*ARR_B)
#define GSMEM   (2*STAGE_B)

__global__ void __launch_bounds__(256) mma_gemm_kernel(float* __restrict__ Cout, int mode)
{
    extern __shared__ char smem[];
    const uint32_t sb0 = smem_u32(smem);
    const int tid  = threadIdx.x;
    const int wid  = tid >> 5, lane = tid & 31;
    const int wRow = wid >> 2, wCol = wid & 3;

    const int nt = blockIdx.x;
    const int m0 = blockIdx.y * 128;
    int wsel, e0;
    if (mode == 0) { wsel = nt >> 3; e0 = (nt & 7) << 7; }
    else           { wsel = 5;       e0 = nt << 7; }

    const bool useAl = (mode != 0);                    // Al*Bh pass
    const bool useBl = (mode != 0) || (wsel == 4);     // Ah*Bl pass

    const __half* Ah = (mode == 0 ? g_xh : g_x2h) + (size_t)m0*DD;
    const __half* Al = (mode == 0 ? g_xl : g_x2l) + (size_t)m0*DD;
    const __half* Bh = g_wth + (size_t)wsel*DD*DD + (size_t)e0*DD;
    const __half* Bl = g_wtl + (size_t)wsel*DD*DD + (size_t)e0*DD;

    const uint32_t aoff = (uint32_t)((wRow*64 + (lane & 15))*ROWB + (lane >> 4)*16);
    const uint32_t boff = (uint32_t)((wCol*32 + (lane & 7) + ((lane >> 4) << 3))*ROWB
                                     + ((lane >> 3) & 1)*16);

    float acc[16][4];
    #pragma unroll
    for (int i = 0; i < 16; i++)
        #pragma unroll
        for (int j = 0; j < 4; j++) acc[i][j] = 0.f;

    auto load_stage = [&](int chunk, uint32_t sb){
        const int kc0 = chunk * KC;
        #pragma unroll
        for (int p = 0; p < 2; p++) {
            int seg = tid + p*256;
            int row = seg >> 2, c = seg & 3;
            uint32_t so = (uint32_t)(row*ROWB + c*16);
            size_t   go = (size_t)row*DD + kc0 + c*8;
            cp16(sb + ST_AH + so, Ah + go);
            if (useAl) cp16(sb + ST_AL + so, Al + go);
            cp16(sb + ST_BH + so, Bh + go);
            if (useBl) cp16(sb + ST_BL + so, Bl + go);
        }
        cp_commit();
    };

    load_stage(0, sb0);

    for (int i = 0; i < NCHUNK; i++) {
        const int st = i & 1;
        if (i + 1 < NCHUNK) { load_stage(i + 1, sb0 + ((i+1)&1)*STAGE_B); cp_wait1(); }
        else                { cp_wait0(); }
        __syncthreads();

        const uint32_t sb = sb0 + st*STAGE_B;
        #pragma unroll
        for (int ks = 0; ks < 2; ks++) {
            uint32_t ah[16], al[16], bh[8], bl[8];
            #pragma unroll
            for (int mi = 0; mi < 4; mi++) {
                ldsm4(ah + mi*4, sb + ST_AH + aoff + mi*16*ROWB + ks*32);
                if (useAl) ldsm4(al + mi*4, sb + ST_AL + aoff + mi*16*ROWB + ks*32);
            }
            #pragma unroll
            for (int nt2 = 0; nt2 < 2; nt2++) {
                ldsm4(bh + nt2*4, sb + ST_BH + boff + nt2*16*ROWB + ks*32);
                if (useBl) ldsm4(bl + nt2*4, sb + ST_BL + boff + nt2*16*ROWB + ks*32);
            }
            #pragma unroll
            for (int mi = 0; mi < 4; mi++)
                #pragma unroll
                for (int ni = 0; ni < 4; ni++) {
                    mma16816(acc[mi*4+ni], ah + mi*4, bh + ni*2);
                    if (useBl) mma16816(acc[mi*4+ni], ah + mi*4, bl + ni*2);
                    if (useAl) mma16816(acc[mi*4+ni], al + mi*4, bh + ni*2);
                }
        }
        __syncthreads();
    }

    // -------- accum -> SMEM (stride 132 floats) --------
    float* Cs = (float*)smem;
    #pragma unroll
    for (int mi = 0; mi < 4; mi++)
        #pragma unroll
        for (int ni = 0; ni < 4; ni++) {
            int r = wRow*64 + mi*16 + (lane >> 2);
            int c = wCol*32 + ni*8  + (lane & 3)*2;
            *(float2*)&Cs[r*132 + c]     = make_float2(acc[mi*4+ni][0], acc[mi*4+ni][1]);
            *(float2*)&Cs[(r+8)*132 + c] = make_float2(acc[mi*4+ni][2], acc[mi*4+ni][3]);
        }
    __syncthreads();

    // -------- route to gmem --------
    const int cw = tid >> 5, ln = tid & 31;
    if (mode == 0) {
        const int b = m0 >> 11, s0 = m0 & 2047;
        const float sc = (wsel < 2) ? 0.125f : 1.0f;
        __half* dst;
        if      (wsel < 2) dst = g_qh + ((size_t)wsel*BB + b)*HH*(size_t)SS*HDIM;
        else if (wsel < 4) dst = g_kh + ((size_t)(wsel-2)*BB + b)*HH*(size_t)SS*HDIM;
        else               dst = g_vh + (size_t)b*HH*(size_t)SS*HDIM;
        #pragma unroll 4
        for (int rp = 0; rp < 16; rp++) {
            int r = rp*8 + cw, c4 = ln*4;
            int e = e0 + c4, h = e >> 6, hd = e & 63;
            __half2 p0 = __floats2half2_rn(Cs[r*132+c4]*sc,   Cs[r*132+c4+1]*sc);
            __half2 p1 = __floats2half2_rn(Cs[r*132+c4+2]*sc, Cs[r*132+c4+3]*sc);
            uint2 u; u.x = *(uint32_t*)&p0; u.y = *(uint32_t*)&p1;
            *(uint2*)&dst[((size_t)h*SS + s0 + r)*HDIM + hd] = u;
        }
    } else {
        #pragma unroll 4
        for (int rp = 0; rp < 16; rp++) {
            int r = rp*8 + cw, c4 = ln*4;
            float4 v = make_float4(Cs[r*132+c4], Cs[r*132+c4+1], Cs[r*132+c4+2], Cs[r*132+c4+3]);
            *(float4*)&Cout[(size_t)(m0 + r)*DD + e0 + c4] = v;
        }
    }
}

// ================= fused dual-branch HMMA flash attention ==================
// CTA: 64 q-rows, BOTH diff branches. Warps 0-3 branch 0, warps 4-7 branch 1.
// Shared V per stage; epilogue computes lam*(O0-O1), writes g_od, and
// accumulates GroupNorm stats via atomics (stats kernel eliminated).
#define FST_K0  0
#define FST_K1  8192
#define FST_V   16384
#define FST_CB  24576
#define FSTG    24832
#define FQOFF   (2*FSTG)        // 49664 (Q0 8KB, Q1 8KB)
#define FSMEM   (FQOFF + 16384) // 66048

__global__ void __launch_bounds__(256, 2) flash_mma_kernel(const float* __restrict__ maskp)
{
    extern __shared__ char fsm[];
    const uint32_t sb0 = smem_u32(fsm);
    const int tid = threadIdx.x, w = tid >> 5, lane = tid & 31;
    const int wg = w >> 2, wi = w & 3;              // branch, warp-in-group
    const int qt = gridDim.x - 1 - blockIdx.x;      // heavy tiles first
    const int bh = blockIdx.y;
    const int b = bh >> 4, h = bh & 15;

    const __half* qp0 = g_qh + (((size_t)(0*BB + b)*HH + h)*SS + (size_t)qt*64)*HDIM;
    const __half* qp1 = g_qh + (((size_t)(1*BB + b)*HH + h)*SS + (size_t)qt*64)*HDIM;
    const __half* kp0 = g_kh + (((size_t)(0*BB + b)*HH + h)*SS)*HDIM;
    const __half* kp1 = g_kh + (((size_t)(1*BB + b)*HH + h)*SS)*HDIM;
    const __half* vhp = g_vh + (((size_t)b*HH + h)*SS)*HDIM;
    const float slope = exp2f(-0.5f*(float)(h+1));

    // ---- Q0+Q1 tiles -> smem (swizzled), async ----
    #pragma unroll
    for (int p = 0; p < 4; p++) {
        int idx = tid + p*256;
        int tile = idx >> 9, rem = idx & 511;
        int row = rem >> 3, g = rem & 7;
        const __half* src = tile ? qp1 : qp0;
        cp16(sb0 + FQOFF + tile*8192 + row*128 + ((g ^ (row & 7))*16),
             src + row*64 + g*8);
    }

    auto prefetch = [&](int kt){
        const int stOff = (kt & 1)*FSTG;
        const uint32_t sb = sb0 + stOff;
        const int kbase = kt*64;
        #pragma unroll
        for (int p = 0; p < 6; p++) {
            int idx = tid + p*256;
            int arr = idx >> 9, rem = idx & 511;
            int row = rem >> 3, g = rem & 7;
            const __half* src = (arr == 0) ? kp0 : (arr == 1) ? kp1 : vhp;
            uint32_t swo = (uint32_t)(arr*8192 + row*128 + ((g ^ (row & 7))*16));
            cp16(sb + swo, src + (size_t)(kbase + row)*64 + g*8);
        }
        cp_commit();
        if (tid < 64) {
            int kpos = kbase + tid;
            float mk = maskp[b*SS + kpos];
            ((float*)(fsm + stOff + FST_CB))[tid] = slope*(float)kpos - 1e9f*(1.f - mk);
        }
    };

    prefetch(0);   // group also covers Q loads

    uint32_t qf[4][4];
    float o[8][4];
    #pragma unroll
    for (int j = 0; j < 8; j++)
        #pragma unroll
        for (int c = 0; c < 4; c++) o[j][c] = 0.f;
    float m0 = -1e30f, m1 = -1e30f, l0 = 0.f, l1 = 0.f;

    const int qWmin = qt*64 + wi*16;
    const int qpos0 = qWmin + (lane >> 2);

    const int nkt = qt + 1;
    for (int kt = 0; kt < nkt; kt++) {
        if (kt + 1 < nkt) { prefetch(kt + 1); cp_wait1(); }
        else              { cp_wait0(); }
        __syncthreads();

        if (kt == 0) {
            #pragma unroll
            for (int kc = 0; kc < 4; kc++) {
                int row = wi*16 + (lane & 15);
                int g = kc*2 + (lane >> 4);
                ldsm4(qf[kc], sb0 + FQOFF + wg*8192 + row*128 + ((g ^ (row & 7))*16));
            }
        }

        const int kbase = kt*64;
        const bool skip = (kbase > qWmin + 15);
        if (!skip) {
            const int stOff = (kt & 1)*FSTG;
            const uint32_t sbK = sb0 + stOff + wg*8192;   // K0 or K1
            const uint32_t sbV = sb0 + stOff + FST_V;
            const float* cbp = (const float*)(fsm + stOff + FST_CB);

            // ---- S = Q K^T ----
            float s[8][4];
            #pragma unroll
            for (int j = 0; j < 8; j++)
                #pragma unroll
                for (int c = 0; c < 4; c++) s[j][c] = 0.f;
            #pragma unroll
            for (int kc = 0; kc < 4; kc++) {
                uint32_t kb[16];
                #pragma unroll
                for (int T = 0; T < 4; T++) {
                    int krow = T*16 + (lane & 7) + ((lane >> 4) << 3);
                    int g = kc*2 + ((lane >> 3) & 1);
                    ldsm4(kb + T*4, sbK + krow*128 + ((g ^ (krow & 7))*16));
                }
                #pragma unroll
                for (int j = 0; j < 8; j++)
                    mma16816(s[j], qf[kc], kb + (j >> 1)*4 + (j & 1)*2);
            }

            // ---- col bias + causal + online softmax ----
            const bool needC = (kbase + 63 > qWmin);
            float vm0 = -1e30f, vm1 = -1e30f;
            #pragma unroll
            for (int j = 0; j < 8; j++) {
                int cc = j*8 + ((lane & 3) << 1);
                float2 cb = *(const float2*)&cbp[cc];
                int kpos = kbase + cc;
                s[j][0] += cb.x;
                s[j][1] += cb.y;
                s[j][2] += cb.x;
                s[j][3] += cb.y;
                if (needC) {
                    if (kpos     > qpos0)     s[j][0] = -1e9f;
                    if (kpos + 1 > qpos0)     s[j][1] = -1e9f;
                    if (kpos     > qpos0 + 8) s[j][2] = -1e9f;
                    if (kpos + 1 > qpos0 + 8) s[j][3] = -1e9f;
                }
                vm0 = fmaxf(vm0, fmaxf(s[j][0], s[j][1]));
                vm1 = fmaxf(vm1, fmaxf(s[j][2], s[j][3]));
            }
            vm0 = fmaxf(vm0, __shfl_xor_sync(0xffffffffu, vm0, 1));
            vm0 = fmaxf(vm0, __shfl_xor_sync(0xffffffffu, vm0, 2));
            vm1 = fmaxf(vm1, __shfl_xor_sync(0xffffffffu, vm1, 1));
            vm1 = fmaxf(vm1, __shfl_xor_sync(0xffffffffu, vm1, 2));

            float mn0 = fmaxf(m0, vm0), mn1 = fmaxf(m1, vm1);
            float a0 = __expf(m0 - mn0), a1 = __expf(m1 - mn1);
            m0 = mn0; m1 = mn1;

            float rs0 = 0.f, rs1 = 0.f;
            #pragma unroll
            for (int j = 0; j < 8; j++) {
                s[j][0] = __expf(s[j][0] - mn0); rs0 += s[j][0];
                s[j][1] = __expf(s[j][1] - mn0); rs0 += s[j][1];
                s[j][2] = __expf(s[j][2] - mn1); rs1 += s[j][2];
                s[j][3] = __expf(s[j][3] - mn1); rs1 += s[j][3];
            }
            rs0 += __shfl_xor_sync(0xffffffffu, rs0, 1);
            rs0 += __shfl_xor_sync(0xffffffffu, rs0, 2);
            rs1 += __shfl_xor_sync(0xffffffffu, rs1, 1);
            rs1 += __shfl_xor_sync(0xffffffffu, rs1, 2);
            l0 = l0*a0 + rs0;
            l1 = l1*a1 + rs1;
            #pragma unroll
            for (int j = 0; j < 8; j++) {
                o[j][0] *= a0; o[j][1] *= a0;
                o[j][2] *= a1; o[j][3] *= a1;
            }

            // ---- O += P * V ----
            #pragma unroll
            for (int kc = 0; kc < 4; kc++) {
                uint32_t pf[4];
                pf[0] = packh2(s[2*kc][0],   s[2*kc][1]);
                pf[1] = packh2(s[2*kc][2],   s[2*kc][3]);
                pf[2] = packh2(s[2*kc+1][0], s[2*kc+1][1]);
                pf[3] = packh2(s[2*kc+1][2], s[2*kc+1][3]);
                uint32_t vh[16];
                #pragma unroll
                for (int T = 0; T < 4; T++) {
                    int krow = kc*16 + (lane & 15);
                    int g = T*2 + (lane >> 4);
                    uint32_t ad = (uint32_t)(krow*128 + ((g ^ (krow & 7))*16));
                    ldsm4t(vh + T*4, sbV + ad);
                }
                #pragma unroll
                for (int j = 0; j < 8; j++)
                    mma16816(o[j], pf, vh + (j >> 1)*4 + (j & 1)*2);
            }
        }
        __syncthreads();
    }

    // ---- epilogue: combine branches, write g_od, accumulate stats ----
    const float il0 = 1.f / l0, il1 = 1.f / l1;
    const float lam = g_lamb[h];
    float* Cs = (float*)fsm;                       // 64 x 66 staging (16.9KB)
    const int rl = wi*16 + (lane >> 2);            // local row 0..63

    if (wg == 1) {
        #pragma unroll
        for (int j = 0; j < 8; j++) {
            int c = j*8 + ((lane & 3) << 1);
            *(float2*)&Cs[rl*66 + c]     = make_float2(o[j][0]*il0, o[j][1]*il0);
            *(float2*)&Cs[(rl+8)*66 + c] = make_float2(o[j][2]*il1, o[j][3]*il1);
        }
    }
    __syncthreads();

    float* wsq = (float*)(fsm + FQOFF);            // ws[0..3], wq[0..7]
    if (wg == 0) {
        float* op = g_od + (((size_t)b*HH + h)*SS + (size_t)qt*64)*HDIM;
        float s_ = 0.f, q_ = 0.f;
        #pragma unroll
        for (int j = 0; j < 8; j++) {
            int c = j*8 + ((lane & 3) << 1);
            float d0 = lam*(o[j][0]*il0 - Cs[rl*66 + c]);
            float d1 = lam*(o[j][1]*il0 - Cs[rl*66 + c + 1]);
            float d2 = lam*(o[j][2]*il1 - Cs[(rl+8)*66 + c]);
            float d3 = lam*(o[j][3]*il1 - Cs[(rl+8)*66 + c + 1]);
            *(float2*)&op[(size_t)rl*64 + c]     = make_float2(d0, d1);
            *(float2*)&op[(size_t)(rl+8)*64 + c] = make_float2(d2, d3);
            s_ += d0 + d1 + d2 + d3;
            q_ += d0*d0 + d1*d1 + d2*d2 + d3*d3;
        }
        #pragma unroll
        for (int off = 16; off; off >>= 1) {
            s_ += __shfl_xor_sync(0xffffffffu, s_, off);
            q_ += __shfl_xor_sync(0xffffffffu, q_, off);
        }
        if (lane == 0) { wsq[wi] = s_; wsq[4 + wi] = q_; }
    }
    __syncthreads();
    if (tid == 0) {
        float S_ = wsq[0] + wsq[1] + wsq[2] + wsq[3];
        float Q_ = wsq[4] + wsq[5] + wsq[6] + wsq[7];
        atomicAdd(&g_stats[bh*2],   S_);
        atomicAdd(&g_stats[bh*2+1], Q_);
    }
}

// ---------------- lambda + stats-zero (must precede flash) ------------------
__global__ void lamb_kernel(const float* __restrict__ lq, const float* __restrict__ lk)
{
    int t = threadIdx.x;
    if (t < BB*HH*2) g_stats[t] = 0.f;
    if (t < HH) {
        float s0 = 0.f, s1 = 0.f;
        #pragma unroll 8
        for (int d = 0; d < HDIM; d++) {
            s0 += lq[t*HDIM + d]      * lk[t*HDIM + d];
            s1 += lq[(HH+t)*HDIM + d] * lk[(HH+t)*HDIM + d];
        }
        g_lamb[t] = 0.8f + expf(s0) - expf(s1);
    }
}

// ---------------- normalize + relayout -> fp16 hi/lo -----------------------
__global__ void __launch_bounds__(256) norm_kernel(
    const float* __restrict__ gw, const float* __restrict__ gb)
{
    const int idx = (blockIdx.x*256 + threadIdx.x)*4;
    const int hd  = idx & 63;
    const int tmp = idx >> 6;
    const int s   = tmp & 2047;
    const int bh  = tmp >> 11;
    const int h = bh & 15, b = bh >> 4;

    float4 d4 = *(const float4*)&g_od[idx];

    const float cnt = (float)(SS*HDIM);
    float mean = g_stats[bh*2] / cnt;
    float var  = g_stats[bh*2+1] / cnt - mean*mean;
    float inv  = rsqrtf(var + 1e-5f);

    const int gidx = h*64 + hd;
    float r[4];
    r[0] = (d4.x - mean)*inv*gw[gidx+0] + gb[gidx+0];
    r[1] = (d4.y - mean)*inv*gw[gidx+1] + gb[gidx+1];
    r[2] = (d4.z - mean)*inv*gw[gidx+2] + gb[gidx+2];
    r[3] = (d4.w - mean)*inv*gw[gidx+3] + gb[gidx+3];

    __half hi[4], lo[4];
    #pragma unroll
    for (int c = 0; c < 4; c++) {
        hi[c] = __float2half_rn(r[c]);
        lo[c] = __float2half_rn(r[c] - __half2float(hi[c]));
    }
    size_t d = ((size_t)(b*SS + s))*DD + gidx;
    *(__half2*)&g_x2h[d]   = __halves2half2(hi[0], hi[1]);
    *(__half2*)&g_x2h[d+2] = __halves2half2(hi[2], hi[3]);
    *(__half2*)&g_x2l[d]   = __halves2half2(lo[0], lo[1]);
    *(__half2*)&g_x2l[d+2] = __halves2half2(lo[2], lo[3]);
}

// ---------------- launch ----------------------------------------------------
extern "C" void kernel_launch(void* const* d_in, const int* in_sizes, int n_in,
                              void* d_out, int out_size)
{
    (void)in_sizes; (void)n_in; (void)out_size;
    const float* X    = (const float*)d_in[0];
    const float* mask = (const float*)d_in[1];
    const float* qw   = (const float*)d_in[2];
    const float* kw   = (const float*)d_in[3];
    const float* vw   = (const float*)d_in[4];
    const float* ow   = (const float*)d_in[5];
    const float* lq   = (const float*)d_in[6];
    const float* lk   = (const float*)d_in[7];
    const float* gw   = (const float*)d_in[8];
    const float* gb   = (const float*)d_in[9];
    float* out = (float*)d_out;

    cudaFuncSetAttribute(mma_gemm_kernel,
                         cudaFuncAttributeMaxDynamicSharedMemorySize, GSMEM);
    cudaFuncSetAttribute(flash_mma_kernel,
                         cudaFuncAttributeMaxDynamicSharedMemorySize, FSMEM);

    convert_x_kernel<<<(MM*DD)/1024, 256>>>(X);
    wtrans_kernel   <<<dim3(32, 32, 6), 256>>>(qw, kw, vw, ow);
    lamb_kernel     <<<1, 64>>>(lq, lk);
    mma_gemm_kernel <<<dim3(40, 32), 256, GSMEM>>>(nullptr, 0);
    flash_mma_kernel<<<dim3(SS/64, BB*HH), 256, FSMEM>>>(mask);
    norm_kernel     <<<(BB*HH*SS*HDIM)/1024, 256>>>(gw, gb);
    mma_gemm_kernel <<<dim3(8, 32), 256, GSMEM>>>(out, 1);
}

// round 16
// speedup vs baseline: 1.7526x; 1.7526x over previous
#include <cuda_runtime.h>
#include <cuda_fp16.h>
#include <math.h>
#include <stdint.h>

#define BB   2
#define SS   2048
#define DD   1024
#define HH   16
#define HDIM 64
#define ND   2
#define MM   (BB*SS)

// ---------------- scratch (device globals; no allocation allowed) ----------
__device__ float g_o [ND*BB*HH*SS*HDIM];   // per-branch attention outputs
__device__ float g_lamb[HH];
__device__ float g_stats[BB*HH*2];

__device__ __half g_xh [MM*DD];            // X fp16 (hi only)
__device__ __half g_wth[6*DD*DD];          // W^T hi/lo: [q0,q1,k0,k1,v,o][n][k]
__device__ __half g_wtl[6*DD*DD];
__device__ __half g_x2h[MM*DD];            // normed activations fp16

__device__ __half g_qh [ND*BB*HH*SS*HDIM]; // Q fp16, pre-scaled by 0.125
__device__ __half g_kh [ND*BB*HH*SS*HDIM]; // K fp16 (s,hd)
__device__ __half g_vh [BB*HH*SS*HDIM];    // V fp16

// ====================== PTX helpers (sm_80-baseline only) ==================
__device__ __forceinline__ uint32_t smem_u32(const void* p){
    uint32_t a;
    asm("{ .reg .u64 t; cvta.to.shared.u64 t, %1; cvt.u32.u64 %0, t; }"
        : "=r"(a) : "l"(p));
    return a;
}
__device__ __forceinline__ void cp16(uint32_t s, const void* g){
    asm volatile("cp.async.cg.shared.global [%0], [%1], 16;" :: "r"(s), "l"(g));
}
__device__ __forceinline__ void cp_commit(){ asm volatile("cp.async.commit_group;" ::: "memory"); }
__device__ __forceinline__ void cp_wait0(){ asm volatile("cp.async.wait_group 0;" ::: "memory"); }
__device__ __forceinline__ void cp_wait1(){ asm volatile("cp.async.wait_group 1;" ::: "memory"); }

__device__ __forceinline__ void ldsm4(uint32_t* r, uint32_t addr){
    asm volatile("ldmatrix.sync.aligned.m8n8.x4.shared.b16 {%0,%1,%2,%3}, [%4];"
        : "=r"(r[0]), "=r"(r[1]), "=r"(r[2]), "=r"(r[3]) : "r"(addr));
}
__device__ __forceinline__ void ldsm4t(uint32_t* r, uint32_t addr){
    asm volatile("ldmatrix.sync.aligned.m8n8.x4.trans.shared.b16 {%0,%1,%2,%3}, [%4];"
        : "=r"(r[0]), "=r"(r[1]), "=r"(r[2]), "=r"(r[3]) : "r"(addr));
}
__device__ __forceinline__ void mma16816(float* c, const uint32_t* a, const uint32_t* b){
    asm volatile(
        "mma.sync.aligned.m16n8k16.row.col.f32.f16.f16.f32 "
        "{%0,%1,%2,%3}, {%4,%5,%6,%7}, {%8,%9}, {%0,%1,%2,%3};"
        : "+f"(c[0]), "+f"(c[1]), "+f"(c[2]), "+f"(c[3])
        : "r"(a[0]), "r"(a[1]), "r"(a[2]), "r"(a[3]), "r"(b[0]), "r"(b[1]));
}
__device__ __forceinline__ uint32_t packh2(float a, float b){
    __half2 h = __floats2half2_rn(a, b);
    return *(uint32_t*)&h;
}

// ====================== prep: X -> fp16 ====================================
__global__ void __launch_bounds__(256) convert_x_kernel(const float* __restrict__ X)
{
    int i = (blockIdx.x*256 + threadIdx.x)*4;
    float4 v = *(const float4*)&X[i];
    __half2 h0 = __floats2half2_rn(v.x, v.y);
    __half2 h1 = __floats2half2_rn(v.z, v.w);
    uint2 u; u.x = *(uint32_t*)&h0; u.y = *(uint32_t*)&h1;
    *(uint2*)&g_xh[i] = u;
}

// ====================== prep: W -> W^T fp16 hi/lo ==========================
__global__ void __launch_bounds__(256) wtrans_kernel(
    const float* __restrict__ qw, const float* __restrict__ kw,
    const float* __restrict__ vw, const float* __restrict__ ow)
{
    __shared__ float t[32][33];
    const int w = blockIdx.z;
    const float* src;
    if      (w == 0) src = qw;
    else if (w == 1) src = qw + (size_t)DD*DD;
    else if (w == 2) src = kw;
    else if (w == 3) src = kw + (size_t)DD*DD;
    else if (w == 4) src = vw;
    else             src = ow;

    const int nb = blockIdx.x*32, kb = blockIdx.y*32;
    const int tx = threadIdx.x & 31, ty = threadIdx.x >> 5;

    #pragma unroll
    for (int i = 0; i < 4; i++)
        t[ty + i*8][tx] = src[(size_t)(kb + ty + i*8)*DD + nb + tx];
    __syncthreads();
    #pragma unroll
    for (int i = 0; i < 4; i++) {
        float v = t[tx][ty + i*8];
        __half hi = __float2half_rn(v);
        __half lo = __float2half_rn(v - __half2float(hi));
        size_t d = (size_t)w*DD*DD + (size_t)(nb + ty + i*8)*DD + kb + tx;
        g_wth[d] = hi;
        g_wtl[d] = lo;
    }
}

// ====================== HMMA 2-pass GEMM (Ah*Bh + Ah*Bl), KC=64 ============
#define KC      64
#define NCHUNK  (DD/KC)         // 16
#define ROWB    144             // 128B data + 16B pad; ldsm conflict-free
#define ARR_B   (128*ROWB)      // 18432
#define ST_AH   0
#define ST_BH   (ARR_B)
#define ST_BL   (2*ARR_B)
#define STAGE_B (3*ARR_B)       // 55296
#define GSMEM   (2*STAGE_B)     // 110592 (covers 128x132 f32 epilogue)

__global__ void __launch_bounds__(256) mma_gemm_kernel(float* __restrict__ Cout, int mode)
{
    extern __shared__ char smem[];
    const uint32_t sb0 = smem_u32(smem);
    const int tid  = threadIdx.x;
    const int wid  = tid >> 5, lane = tid & 31;
    const int wRow = wid >> 2, wCol = wid & 3;

    const int nt = blockIdx.x;
    const int m0 = blockIdx.y * 128;
    int wsel, e0;
    if (mode == 0) { wsel = nt >> 3; e0 = (nt & 7) << 7; }
    else           { wsel = 5;       e0 = nt << 7; }

    const __half* Ah = (mode == 0 ? g_xh : g_x2h) + (size_t)m0*DD;
    const __half* Bh = g_wth + (size_t)wsel*DD*DD + (size_t)e0*DD;
    const __half* Bl = g_wtl + (size_t)wsel*DD*DD + (size_t)e0*DD;

    const uint32_t aoff = (uint32_t)((wRow*64 + (lane & 15))*ROWB + (lane >> 4)*16);
    const uint32_t boff = (uint32_t)((wCol*32 + (lane & 7) + ((lane >> 4) << 3))*ROWB
                                     + ((lane >> 3) & 1)*16);

    float acc[16][4];
    #pragma unroll
    for (int i = 0; i < 16; i++)
        #pragma unroll
        for (int j = 0; j < 4; j++) acc[i][j] = 0.f;

    auto load_stage = [&](int chunk, uint32_t sb){
        const int kc0 = chunk * KC;
        #pragma unroll
        for (int p = 0; p < 4; p++) {
            int seg = tid + p*256;              // 1024 segs per array
            int row = seg >> 3, s = seg & 7;    // 8 x 16B data per row
            uint32_t so = (uint32_t)(row*ROWB + s*16);
            size_t   go = (size_t)row*DD + kc0 + s*8;
            cp16(sb + ST_AH + so, Ah + go);
            cp16(sb + ST_BH + so, Bh + go);
            cp16(sb + ST_BL + so, Bl + go);
        }
        cp_commit();
    };

    load_stage(0, sb0);

    for (int i = 0; i < NCHUNK; i++) {
        const int st = i & 1;
        if (i + 1 < NCHUNK) { load_stage(i + 1, sb0 + ((i+1)&1)*STAGE_B); cp_wait1(); }
        else                { cp_wait0(); }
        __syncthreads();

        const uint32_t sb = sb0 + st*STAGE_B;
        #pragma unroll
        for (int ks = 0; ks < 4; ks++) {
            uint32_t ah[16], bh[8], bl[8];
            #pragma unroll
            for (int mi = 0; mi < 4; mi++)
                ldsm4(ah + mi*4, sb + ST_AH + aoff + mi*16*ROWB + ks*32);
            #pragma unroll
            for (int nt2 = 0; nt2 < 2; nt2++) {
                ldsm4(bh + nt2*4, sb + ST_BH + boff + nt2*16*ROWB + ks*32);
                ldsm4(bl + nt2*4, sb + ST_BL + boff + nt2*16*ROWB + ks*32);
            }
            #pragma unroll
            for (int mi = 0; mi < 4; mi++)
                #pragma unroll
                for (int ni = 0; ni < 4; ni++) {
                    mma16816(acc[mi*4+ni], ah + mi*4, bh + ni*2);
                    mma16816(acc[mi*4+ni], ah + mi*4, bl + ni*2);
                }
        }
        __syncthreads();
    }

    // -------- accum -> SMEM (stride 132 floats) --------
    float* Cs = (float*)smem;
    #pragma unroll
    for (int mi = 0; mi < 4; mi++)
        #pragma unroll
        for (int ni = 0; ni < 4; ni++) {
            int r = wRow*64 + mi*16 + (lane >> 2);
            int c = wCol*32 + ni*8  + (lane & 3)*2;
            *(float2*)&Cs[r*132 + c]     = make_float2(acc[mi*4+ni][0], acc[mi*4+ni][1]);
            *(float2*)&Cs[(r+8)*132 + c] = make_float2(acc[mi*4+ni][2], acc[mi*4+ni][3]);
        }
    __syncthreads();

    // -------- route to gmem --------
    const int cw = tid >> 5, ln = tid & 31;
    if (mode == 0) {
        const int b = m0 >> 11, s0 = m0 & 2047;
        const float sc = (wsel < 2) ? 0.125f : 1.0f;
        __half* dst;
        if      (wsel < 2) dst = g_qh + ((size_t)wsel*BB + b)*HH*(size_t)SS*HDIM;
        else if (wsel < 4) dst = g_kh + ((size_t)(wsel-2)*BB + b)*HH*(size_t)SS*HDIM;
        else               dst = g_vh + (size_t)b*HH*(size_t)SS*HDIM;
        #pragma unroll 4
        for (int rp = 0; rp < 16; rp++) {
            int r = rp*8 + cw, c4 = ln*4;
            int e = e0 + c4, h = e >> 6, hd = e & 63;
            __half2 p0 = __floats2half2_rn(Cs[r*132+c4]*sc,   Cs[r*132+c4+1]*sc);
            __half2 p1 = __floats2half2_rn(Cs[r*132+c4+2]*sc, Cs[r*132+c4+3]*sc);
            uint2 u; u.x = *(uint32_t*)&p0; u.y = *(uint32_t*)&p1;
            *(uint2*)&dst[((size_t)h*SS + s0 + r)*HDIM + hd] = u;
        }
    } else {
        #pragma unroll 4
        for (int rp = 0; rp < 16; rp++) {
            int r = rp*8 + cw, c4 = ln*4;
            float4 v = make_float4(Cs[r*132+c4], Cs[r*132+c4+1], Cs[r*132+c4+2], Cs[r*132+c4+3]);
            *(float4*)&Cout[(size_t)(m0 + r)*DD + e0 + c4] = v;
        }
    }
}

// ================= HMMA flash attention (R12 proven version) ===============
// CTA: 128 q-rows x 64 k-cols/iter; 8 warps x 16 rows. fp16 QK^T, P*Vh.
#define FST_K   0
#define FST_VH  8192
#define FST_CB  16384
#define FSTG    16640
#define FQOFF   (2*FSTG)        // 33280
#define FSMEM   (FQOFF + 16384) // 49664

__global__ void __launch_bounds__(256, 2) flash_mma_kernel(const float* __restrict__ maskp)
{
    extern __shared__ char fsm[];
    const uint32_t sb0 = smem_u32(fsm);
    const int tid = threadIdx.x, w = tid >> 5, lane = tid & 31;
    const int qt = gridDim.x - 1 - blockIdx.x;      // heavy tiles first
    const int bh = blockIdx.y, n = blockIdx.z;
    const int b = bh >> 4, h = bh & 15;

    const __half* qp  = g_qh + (((size_t)(n*BB + b)*HH + h)*SS + (size_t)qt*128)*HDIM;
    const __half* kp  = g_kh + (((size_t)(n*BB + b)*HH + h)*SS)*HDIM;
    const __half* vhp = g_vh + (((size_t)b*HH + h)*SS)*HDIM;
    const float slope = exp2f(-0.5f*(float)(h+1));

    // ---- Q tile -> smem (swizzled), async ----
    #pragma unroll
    for (int p = 0; p < 4; p++) {
        int idx = tid + p*256;
        int row = idx >> 3, g = idx & 7;
        cp16(sb0 + FQOFF + row*128 + ((g ^ (row & 7))*16), qp + row*64 + g*8);
    }

    auto prefetch = [&](int kt){
        const int stOff = (kt & 1)*FSTG;
        const uint32_t sb = sb0 + stOff;
        const int kbase = kt*64;
        #pragma unroll
        for (int p = 0; p < 2; p++) {
            int idx = tid + p*256;
            int row = idx >> 3, g = idx & 7;
            uint32_t swo = (uint32_t)(row*128 + ((g ^ (row & 7))*16));
            size_t go = (size_t)(kbase + row)*64 + g*8;
            cp16(sb + FST_K  + swo, kp  + go);
            cp16(sb + FST_VH + swo, vhp + go);
        }
        cp_commit();
        if (tid < 64) {
            int kpos = kbase + tid;
            float mk = maskp[b*SS + kpos];
            ((float*)(fsm + stOff + FST_CB))[tid] = slope*(float)kpos - 1e9f*(1.f - mk);
        }
    };

    prefetch(0);   // group also covers Q loads

    uint32_t qf[4][4];
    float o[8][4];
    #pragma unroll
    for (int j = 0; j < 8; j++)
        #pragma unroll
        for (int c = 0; c < 4; c++) o[j][c] = 0.f;
    float m0 = -1e30f, m1 = -1e30f, l0 = 0.f, l1 = 0.f;

    const int qWmin = qt*128 + w*16;
    const int qpos0 = qWmin + (lane >> 2);

    const int nkt = 2*qt + 2;
    for (int kt = 0; kt < nkt; kt++) {
        if (kt + 1 < nkt) { prefetch(kt + 1); cp_wait1(); }
        else              { cp_wait0(); }
        __syncthreads();

        if (kt == 0) {
            #pragma unroll
            for (int kc = 0; kc < 4; kc++) {
                int row = w*16 + (lane & 15);
                int g = kc*2 + (lane >> 4);
                ldsm4(qf[kc], sb0 + FQOFF + row*128 + ((g ^ (row & 7))*16));
            }
        }

        const int kbase = kt*64;
        const bool skip = (kbase > qWmin + 15);
        if (!skip) {
            const int stOff = (kt & 1)*FSTG;
            const uint32_t sbK  = sb0 + stOff + FST_K;
            const uint32_t sbVH = sb0 + stOff + FST_VH;
            const float* cbp = (const float*)(fsm + stOff + FST_CB);

            // ---- S = Q K^T ----
            float s[8][4];
            #pragma unroll
            for (int j = 0; j < 8; j++)
                #pragma unroll
                for (int c = 0; c < 4; c++) s[j][c] = 0.f;
            #pragma unroll
            for (int kc = 0; kc < 4; kc++) {
                uint32_t kb[16];
                #pragma unroll
                for (int T = 0; T < 4; T++) {
                    int krow = T*16 + (lane & 7) + ((lane >> 4) << 3);
                    int g = kc*2 + ((lane >> 3) & 1);
                    ldsm4(kb + T*4, sbK + krow*128 + ((g ^ (krow & 7))*16));
                }
                #pragma unroll
                for (int j = 0; j < 8; j++)
                    mma16816(s[j], qf[kc], kb + (j >> 1)*4 + (j & 1)*2);
            }

            // ---- col bias + causal + online softmax ----
            const bool needC = (kbase + 63 > qWmin);
            float vm0 = -1e30f, vm1 = -1e30f;
            #pragma unroll
            for (int j = 0; j < 8; j++) {
                int cc = j*8 + ((lane & 3) << 1);
                float2 cb = *(const float2*)&cbp[cc];
                int kpos = kbase + cc;
                s[j][0] += cb.x;
                s[j][1] += cb.y;
                s[j][2] += cb.x;
                s[j][3] += cb.y;
                if (needC) {
                    if (kpos     > qpos0)     s[j][0] = -1e9f;
                    if (kpos + 1 > qpos0)     s[j][1] = -1e9f;
                    if (kpos     > qpos0 + 8) s[j][2] = -1e9f;
                    if (kpos + 1 > qpos0 + 8) s[j][3] = -1e9f;
                }
                vm0 = fmaxf(vm0, fmaxf(s[j][0], s[j][1]));
                vm1 = fmaxf(vm1, fmaxf(s[j][2], s[j][3]));
            }
            vm0 = fmaxf(vm0, __shfl_xor_sync(0xffffffffu, vm0, 1));
            vm0 = fmaxf(vm0, __shfl_xor_sync(0xffffffffu, vm0, 2));
            vm1 = fmaxf(vm1, __shfl_xor_sync(0xffffffffu, vm1, 1));
            vm1 = fmaxf(vm1, __shfl_xor_sync(0xffffffffu, vm1, 2));

            float mn0 = fmaxf(m0, vm0), mn1 = fmaxf(m1, vm1);
            float a0 = __expf(m0 - mn0), a1 = __expf(m1 - mn1);
            m0 = mn0; m1 = mn1;

            float rs0 = 0.f, rs1 = 0.f;
            #pragma unroll
            for (int j = 0; j < 8; j++) {
                s[j][0] = __expf(s[j][0] - mn0); rs0 += s[j][0];
                s[j][1] = __expf(s[j][1] - mn0); rs0 += s[j][1];
                s[j][2] = __expf(s[j][2] - mn1); rs1 += s[j][2];
                s[j][3] = __expf(s[j][3] - mn1); rs1 += s[j][3];
            }
            rs0 += __shfl_xor_sync(0xffffffffu, rs0, 1);
            rs0 += __shfl_xor_sync(0xffffffffu, rs0, 2);
            rs1 += __shfl_xor_sync(0xffffffffu, rs1, 1);
            rs1 += __shfl_xor_sync(0xffffffffu, rs1, 2);
            l0 = l0*a0 + rs0;
            l1 = l1*a1 + rs1;
            #pragma unroll
            for (int j = 0; j < 8; j++) {
                o[j][0] *= a0; o[j][1] *= a0;
                o[j][2] *= a1; o[j][3] *= a1;
            }

            // ---- O += P * Vh ----
            #pragma unroll
            for (int kc = 0; kc < 4; kc++) {
                uint32_t pf[4];
                pf[0] = packh2(s[2*kc][0],   s[2*kc][1]);
                pf[1] = packh2(s[2*kc][2],   s[2*kc][3]);
                pf[2] = packh2(s[2*kc+1][0], s[2*kc+1][1]);
                pf[3] = packh2(s[2*kc+1][2], s[2*kc+1][3]);
                uint32_t vh[16];
                #pragma unroll
                for (int T = 0; T < 4; T++) {
                    int krow = kc*16 + (lane & 15);
                    int g = T*2 + (lane >> 4);
                    uint32_t ad = (uint32_t)(krow*128 + ((g ^ (krow & 7))*16));
                    ldsm4t(vh + T*4, sbVH + ad);
                }
                #pragma unroll
                for (int j = 0; j < 8; j++)
                    mma16816(o[j], pf, vh + (j >> 1)*4 + (j & 1)*2);
            }
        }
        __syncthreads();
    }

    // ---- write O ----
    const float il0 = 1.f / l0, il1 = 1.f / l1;
    float* op = g_o + (((size_t)(n*BB + b)*HH + h)*SS)*HDIM;
    const int rg = qt*128 + w*16 + (lane >> 2);
    #pragma unroll
    for (int j = 0; j < 8; j++) {
        int c = j*8 + ((lane & 3) << 1);
        *(float2*)&op[(size_t)rg*64 + c]     = make_float2(o[j][0]*il0, o[j][1]*il0);
        *(float2*)&op[(size_t)(rg+8)*64 + c] = make_float2(o[j][2]*il1, o[j][3]*il1);
    }
}

// ---------------- lambda + stats-zero -------------------------------------
__global__ void lamb_kernel(const float* __restrict__ lq, const float* __restrict__ lk)
{
    int t = threadIdx.x;
    if (t < BB*HH*2) g_stats[t] = 0.f;
    if (t < HH) {
        float s0 = 0.f, s1 = 0.f;
        #pragma unroll 8
        for (int d = 0; d < HDIM; d++) {
            s0 += lq[t*HDIM + d]      * lk[t*HDIM + d];
            s1 += lq[(HH+t)*HDIM + d] * lk[(HH+t)*HDIM + d];
        }
        g_lamb[t] = 0.8f + expf(s0) - expf(s1);
    }
}

// ---------------- GroupNorm stats ------------------------------------------
__global__ void __launch_bounds__(256) stats_kernel()
{
    const int bh = blockIdx.x;
    const int ch = blockIdx.y;
    const int b = bh >> 4, h = bh & 15;
    const float lam = g_lamb[h];
    const int CHUNK = (SS/8)*HDIM;
    const float* o0 = g_o + (((size_t)b*HH + h)*SS)*HDIM + (size_t)ch*CHUNK;
    const float* o1 = o0 + (size_t)BB*HH*SS*HDIM;

    float s = 0.f, q = 0.f;
    for (int i = threadIdx.x; i < CHUNK; i += 256) {
        float c = lam*(o0[i] - o1[i]);
        s += c; q += c*c;
    }
    #pragma unroll
    for (int off = 16; off; off >>= 1) {
        s += __shfl_xor_sync(0xffffffffu, s, off);
        q += __shfl_xor_sync(0xffffffffu, q, off);
    }
    __shared__ float ws[8], wq[8];
    int w = threadIdx.x >> 5, lane = threadIdx.x & 31;
    if (lane == 0) { ws[w] = s; wq[w] = q; }
    __syncthreads();
    if (threadIdx.x == 0) {
        float S_ = 0.f, Q_ = 0.f;
        #pragma unroll
        for (int i = 0; i < 8; i++) { S_ += ws[i]; Q_ += wq[i]; }
        atomicAdd(&g_stats[bh*2],   S_);
        atomicAdd(&g_stats[bh*2+1], Q_);
    }
}

// ---------------- normalize + relayout -> fp16 -----------------------------
__global__ void __launch_bounds__(256) norm_kernel(
    const float* __restrict__ gw, const float* __restrict__ gb)
{
    const int idx = (blockIdx.x*256 + threadIdx.x)*4;
    const int hd  = idx & 63;
    const int tmp = idx >> 6;
    const int s   = tmp & 2047;
    const int bh  = tmp >> 11;
    const int h = bh & 15, b = bh >> 4;

    const float lam = g_lamb[h];
    float4 a0 = *(const float4*)&g_o[idx];
    float4 a1 = *(const float4*)&g_o[(size_t)BB*HH*SS*HDIM + idx];

    const float cnt = (float)(SS*HDIM);
    float mean = g_stats[bh*2] / cnt;
    float var  = g_stats[bh*2+1] / cnt - mean*mean;
    float inv  = rsqrtf(var + 1e-5f);

    const int gidx = h*64 + hd;
    float r[4];
    r[0] = (lam*(a0.x-a1.x) - mean)*inv*gw[gidx+0] + gb[gidx+0];
    r[1] = (lam*(a0.y-a1.y) - mean)*inv*gw[gidx+1] + gb[gidx+1];
    r[2] = (lam*(a0.z-a1.z) - mean)*inv*gw[gidx+2] + gb[gidx+2];
    r[3] = (lam*(a0.w-a1.w) - mean)*inv*gw[gidx+3] + gb[gidx+3];

    __half2 h0 = __floats2half2_rn(r[0], r[1]);
    __half2 h1 = __floats2half2_rn(r[2], r[3]);
    uint2 u; u.x = *(uint32_t*)&h0; u.y = *(uint32_t*)&h1;
    *(uint2*)&g_x2h[((size_t)(b*SS + s))*DD + gidx] = u;
}

// ---------------- launch ----------------------------------------------------
extern "C" void kernel_launch(void* const* d_in, const int* in_sizes, int n_in,
                              void* d_out, int out_size)
{
    (void)in_sizes; (void)n_in; (void)out_size;
    const float* X    = (const float*)d_in[0];
    const float* mask = (const float*)d_in[1];
    const float* qw   = (const float*)d_in[2];
    const float* kw   = (const float*)d_in[3];
    const float* vw   = (const float*)d_in[4];
    const float* ow   = (const float*)d_in[5];
    const float* lq   = (const float*)d_in[6];
    const float* lk   = (const float*)d_in[7];
    const float* gw   = (const float*)d_in[8];
    const float* gb   = (const float*)d_in[9];
    float* out = (float*)d_out;

    cudaFuncSetAttribute(mma_gemm_kernel,
                         cudaFuncAttributeMaxDynamicSharedMemorySize, GSMEM);
    cudaFuncSetAttribute(flash_mma_kernel,
                         cudaFuncAttributeMaxDynamicSharedMemorySize, FSMEM);

    convert_x_kernel<<<(MM*DD)/1024, 256>>>(X);
    wtrans_kernel   <<<dim3(32, 32, 6), 256>>>(qw, kw, vw, ow);
    mma_gemm_kernel <<<dim3(40, 32), 256, GSMEM>>>(nullptr, 0);
    flash_mma_kernel<<<dim3(SS/128, BB*HH, ND), 256, FSMEM>>>(mask);
    lamb_kernel     <<<1, 64>>>(lq, lk);
    stats_kernel    <<<dim3(BB*HH, 8), 256>>>();
    norm_kernel     <<<(BB*HH*SS*HDIM)/1024, 256>>>(gw, gb);
    mma_gemm_kernel <<<dim3(8, 32), 256, GSMEM>>>(out, 1);
}